// round 14
// baseline (speedup 1.0000x reference)
#include <cuda_runtime.h>
#include <cuda_fp16.h>
#include <cstdint>
#include <cstddef>

// ---------------- problem dims ----------------
#define BDIM 64
#define SDIM 64
#define DDIM 2048
#define HHE  8
#define HD   256
#define INTER 16384
#define ROWS (BDIM*SDIM)            // 4096

// ---------------- scratch (device globals; no allocs allowed) ----------------
__device__ __align__(256) __half g_h1h [ROWS*DDIM];
__device__ __align__(256) __half g_qh  [ROWS*DDIM];
__device__ __align__(256) __half g_kh  [ROWS*HD];
__device__ __align__(256) __half g_vh  [ROWS*HD];
__device__ __align__(256) __half g_aoh [ROWS*DDIM];
__device__ __align__(256) __half g_mlph[(size_t)ROWS*INTER];
// fp16 weight copies
__device__ __align__(256) __half g_wqh[DDIM*DDIM];
__device__ __align__(256) __half g_wkh[HD*DDIM];
__device__ __align__(256) __half g_wvh[HD*DDIM];
__device__ __align__(256) __half g_woh[DDIM*DDIM];
__device__ __align__(256) __half g_wgh[(size_t)INTER*DDIM];
__device__ __align__(256) __half g_wuh[(size_t)INTER*DDIM];
__device__ __align__(256) __half g_wdh[(size_t)DDIM*INTER];

struct __align__(16) half2x4 { __half2 a, b, c, d; };

// ---------------- helpers ----------------
__device__ __forceinline__ void cp16s(uint32_t saddr, const void* gsrc) {
    asm volatile("cp.async.cg.shared.global [%0], [%1], 16;" :: "r"(saddr), "l"(gsrc));
}
#define CP_COMMIT() asm volatile("cp.async.commit_group;")

__device__ __forceinline__ void ldsm4(uint32_t* r, uint32_t a) {
    asm volatile("ldmatrix.sync.aligned.m8n8.x4.shared.b16 {%0,%1,%2,%3}, [%4];"
                 : "=r"(r[0]), "=r"(r[1]), "=r"(r[2]), "=r"(r[3]) : "r"(a));
}
__device__ __forceinline__ void hmma(float* c, const uint32_t* a, const uint32_t* b) {
    asm volatile("mma.sync.aligned.m16n8k16.row.col.f32.f16.f16.f32 "
                 "{%0,%1,%2,%3}, {%4,%5,%6,%7}, {%8,%9}, {%0,%1,%2,%3};"
                 : "+f"(c[0]), "+f"(c[1]), "+f"(c[2]), "+f"(c[3])
                 : "r"(a[0]), "r"(a[1]), "r"(a[2]), "r"(a[3]), "r"(b[0]), "r"(b[1]));
}
__device__ __forceinline__ float gelu_tanh(float x) {
    float t = tanhf(0.7978845608028654f * (x + 0.044715f * x * x * x));
    return 0.5f * x * (1.0f + t);
}

// ---------------- fp32 -> fp16 convert (8 elems/thread) ----------------
__global__ void cvt_h_kernel(const float4* __restrict__ in, half2x4* __restrict__ out, int n8) {
    int i = blockIdx.x * blockDim.x + threadIdx.x;
    if (i >= n8) return;
    float4 v0 = in[2*i], v1 = in[2*i+1];
    half2x4 o;
    o.a = __floats2half2_rn(v0.x, v0.y);
    o.b = __floats2half2_rn(v0.z, v0.w);
    o.c = __floats2half2_rn(v1.x, v1.y);
    o.d = __floats2half2_rn(v1.z, v1.w);
    out[i] = o;
}

// ---------------- rmsnorm (fp16 output for GEMM consumption) ----------------
__global__ __launch_bounds__(256) void rmsnorm_kernel(const float* __restrict__ x,
                                                      const float* __restrict__ w,
                                                      __half2* __restrict__ out) {
    int row = blockIdx.x;
    const float4* x4 = (const float4*)(x + (size_t)row * DDIM);
    const float4* w4 = (const float4*)w;
    __half2* o2 = out + (size_t)row * (DDIM/2);
    int t = threadIdx.x;
    float4 a = x4[t], b = x4[t + 256];
    float s = a.x*a.x + a.y*a.y + a.z*a.z + a.w*a.w
            + b.x*b.x + b.y*b.y + b.z*b.z + b.w*b.w;
    #pragma unroll
    for (int o = 16; o > 0; o >>= 1) s += __shfl_xor_sync(0xffffffffu, s, o);
    __shared__ float red[8];
    if ((t & 31) == 0) red[t >> 5] = s;
    __syncthreads();
    float tot = 0.f;
    #pragma unroll
    for (int i = 0; i < 8; i++) tot += red[i];
    float r = rsqrtf(tot * (1.0f / DDIM) + 1e-6f);
    float4 wa = w4[t], wb = w4[t + 256];
    o2[2*t]          = __floats2half2_rn(a.x*r*(1.f+wa.x), a.y*r*(1.f+wa.y));
    o2[2*t+1]        = __floats2half2_rn(a.z*r*(1.f+wa.z), a.w*r*(1.f+wa.w));
    o2[512 + 2*t]    = __floats2half2_rn(b.x*r*(1.f+wb.x), b.y*r*(1.f+wb.y));
    o2[512 + 2*t+1]  = __floats2half2_rn(b.z*r*(1.f+wb.z), b.w*r*(1.f+wb.w));
}

// ---------------- fp16 tensor-core GEMM (single-B) ----------------
// C(M,N) = A(M,K:half) @ B(N,K:half)^T
// CTA tile 256x256, 16 warps (64x64 each, 4x4), BK=64, 3-stage cp.async.
// mode 1: C = acc + R (fp32)
// mode 3: OH(x) = half(acc)
// blockIdx.z selects (B2, OH2) operands (fused K/V projections).
#define BKT 64
#define NSTAGE 3
#define STAGE_B ((256 + 256) * BKT * 2)     // 65536
#define GEMM_SMEM (NSTAGE * STAGE_B)        // 196608

__global__ __launch_bounds__(512, 1) void gemm_h(
    const __half* __restrict__ A, const __half* __restrict__ Bw,
    const __half* __restrict__ B2,
    float* __restrict__ C,
    const float* __restrict__ R,
    __half* __restrict__ OH, __half* __restrict__ OH2,
    int N, int K, int mode)
{
    extern __shared__ char smem[];
    const uint32_t sbase = (uint32_t)__cvta_generic_to_shared(smem);
    const int tid = threadIdx.x;
    const int lane = tid & 31, warp = tid >> 5;
    const int m0 = blockIdx.x * 256, n0 = blockIdx.y * 256;
    const __half* Bx = blockIdx.z ? B2 : Bw;
    __half* OHx = blockIdx.z ? OH2 : OH;

    const int wm = (warp & 3) * 64;      // 0,64,128,192
    const int wn = (warp >> 2) * 64;     // 0,64,128,192

    const __half* Abase = A + (size_t)m0 * K;
    const __half* Bbase = Bx + (size_t)n0 * K;

    float acc[4][8][4];
    #pragma unroll
    for (int i = 0; i < 4; i++)
        #pragma unroll
        for (int j = 0; j < 8; j++) {
            acc[i][j][0] = 0.f; acc[i][j][1] = 0.f; acc[i][j][2] = 0.f; acc[i][j][3] = 0.f;
        }

    const int KT = K / BKT;
    // 4096 chunks of 16B per stage (A:2048, B:2048), 8 per thread
    #pragma unroll
    for (int p = 0; p < 2; p++) {
        uint32_t st = sbase + p * STAGE_B;
        #pragma unroll
        for (int i = 0; i < 8; i++) {
            int id = tid + (i << 9);
            if (id < 2048) {
                int row = id >> 3, c = id & 7;
                uint32_t soff = row * 128 + (((uint32_t)c ^ (row & 7)) << 4);
                cp16s(st + soff, Abase + (size_t)row * K + p * BKT + c * 8);
            } else {
                int idb = id - 2048;
                int row = idb >> 3, c = idb & 7;
                uint32_t soff = row * 128 + (((uint32_t)c ^ (row & 7)) << 4);
                cp16s(st + 32768 + soff, Bbase + (size_t)row * K + p * BKT + c * 8);
            }
        }
        CP_COMMIT();
    }

    int ldst = 2;   // stage index to load next
    for (int kt = 0; kt < KT; kt++) {
        if (kt + 2 < KT) {
            uint32_t st = sbase + ldst * STAGE_B;
            int koff = (kt + 2) * BKT;
            #pragma unroll
            for (int i = 0; i < 8; i++) {
                int id = tid + (i << 9);
                if (id < 2048) {
                    int row = id >> 3, c = id & 7;
                    uint32_t soff = row * 128 + (((uint32_t)c ^ (row & 7)) << 4);
                    cp16s(st + soff, Abase + (size_t)row * K + koff + c * 8);
                } else {
                    int idb = id - 2048;
                    int row = idb >> 3, c = idb & 7;
                    uint32_t soff = row * 128 + (((uint32_t)c ^ (row & 7)) << 4);
                    cp16s(st + 32768 + soff, Bbase + (size_t)row * K + koff + c * 8);
                }
            }
        }
        CP_COMMIT();
        asm volatile("cp.async.wait_group 2;");
        __syncthreads();

        int cur = ldst + 1; if (cur >= NSTAGE) cur -= NSTAGE;   // == kt % 3
        const uint32_t st = sbase + cur * STAGE_B;
        const uint32_t swz = lane & 7;
        #pragma unroll
        for (int ks = 0; ks < 4; ks++) {
            uint32_t a[4][4], b[8][2];
            #pragma unroll
            for (int mi = 0; mi < 4; mi++) {
                int row = wm + mi * 16 + (lane & 15);
                uint32_t ch = ((uint32_t)(2 * ks + (lane >> 4))) ^ swz;
                ldsm4(a[mi], st + row * 128 + (ch << 4));
            }
            #pragma unroll
            for (int ni = 0; ni < 8; ni += 2) {
                int row = wn + ni * 8 + ((lane >> 4) << 3) + (lane & 7);
                uint32_t ch = ((uint32_t)(2 * ks + ((lane >> 3) & 1))) ^ swz;
                uint32_t r4[4];
                ldsm4(r4, st + 32768 + row * 128 + (ch << 4));
                b[ni][0] = r4[0]; b[ni][1] = r4[1];
                b[ni+1][0] = r4[2]; b[ni+1][1] = r4[3];
            }
            #pragma unroll
            for (int mi = 0; mi < 4; mi++)
                #pragma unroll
                for (int ni = 0; ni < 8; ni++)
                    hmma(acc[mi][ni], a[mi], b[ni]);
        }
        __syncthreads();
        if (++ldst >= NSTAGE) ldst = 0;
    }

    // epilogue
    #pragma unroll
    for (int mi = 0; mi < 4; mi++) {
        #pragma unroll
        for (int ni = 0; ni < 8; ni++) {
            int r0 = m0 + wm + mi * 16 + (lane >> 2);
            int col = n0 + wn + ni * 8 + ((lane & 3) << 1);
            size_t i0 = (size_t)r0 * N + col;
            size_t i1 = i0 + (size_t)8 * N;
            float* cc = acc[mi][ni];
            if (mode == 1) {
                float2 r0v = *(const float2*)(R + i0);
                float2 r1v = *(const float2*)(R + i1);
                *(float2*)(C + i0) = make_float2(cc[0] + r0v.x, cc[1] + r0v.y);
                *(float2*)(C + i1) = make_float2(cc[2] + r1v.x, cc[3] + r1v.y);
            } else {
                *(__half2*)(OHx + i0) = __floats2half2_rn(cc[0], cc[1]);
                *(__half2*)(OHx + i1) = __floats2half2_rn(cc[2], cc[3]);
            }
        }
    }
}

// ---------------- fused gate+up GEMM with gelu-mul epilogue ----------------
// CTA tile 256(M) x 128(N), dual-B, 512 threads, 16 warps (64x32 each, 4x4),
// BK=64, 3-stage cp.async.
#define GU_STAGE ((256 + 128 + 128) * BKT * 2)   // 65536
#define GU_SMEM (3 * GU_STAGE)                   // 196608

__global__ __launch_bounds__(512, 1) void gemm_gateup(
    const __half* __restrict__ A, const __half* __restrict__ Bg,
    const __half* __restrict__ Bu, __half* __restrict__ OH, int K)
{
    extern __shared__ char smem[];
    const uint32_t sbase = (uint32_t)__cvta_generic_to_shared(smem);
    const int tid = threadIdx.x;
    const int lane = tid & 31, warp = tid >> 5;
    const int m0 = blockIdx.x * 256, n0 = blockIdx.y * 128;

    const int wm = (warp & 3) * 64;      // 0,64,128,192
    const int wn = (warp >> 2) * 32;     // 0,32,64,96

    const __half* Abase = A + (size_t)m0 * K;
    const __half* Gbase = Bg + (size_t)n0 * K;
    const __half* Ubase = Bu + (size_t)n0 * K;

    float accg[4][4][4], accu[4][4][4];
    #pragma unroll
    for (int i = 0; i < 4; i++)
        #pragma unroll
        for (int j = 0; j < 4; j++)
            #pragma unroll
            for (int c = 0; c < 4; c++) { accg[i][j][c] = 0.f; accu[i][j][c] = 0.f; }

    const int KT = K / BKT;
    // 4096 chunks/stage: A 0..2047, Bg 2048..3071, Bu 3072..4095; 8 per thread
    #pragma unroll
    for (int p = 0; p < 2; p++) {
        uint32_t st = sbase + p * GU_STAGE;
        #pragma unroll
        for (int i = 0; i < 8; i++) {
            int id = tid + (i << 9);
            int row, c; uint32_t soff; const __half* gb;
            if (id < 2048)      { row = id >> 3;          c = id & 7; gb = Abase; soff = 0; }
            else if (id < 3072) { row = (id - 2048) >> 3; c = id & 7; gb = Gbase; soff = 32768; }
            else                { row = (id - 3072) >> 3; c = id & 7; gb = Ubase; soff = 49152; }
            soff += row * 128 + (((uint32_t)c ^ (row & 7)) << 4);
            cp16s(st + soff, gb + (size_t)row * K + p * BKT + c * 8);
        }
        CP_COMMIT();
    }

    int ldst = 2;
    for (int kt = 0; kt < KT; kt++) {
        if (kt + 2 < KT) {
            uint32_t st = sbase + ldst * GU_STAGE;
            int koff = (kt + 2) * BKT;
            #pragma unroll
            for (int i = 0; i < 8; i++) {
                int id = tid + (i << 9);
                int row, c; uint32_t soff; const __half* gb;
                if (id < 2048)      { row = id >> 3;          c = id & 7; gb = Abase; soff = 0; }
                else if (id < 3072) { row = (id - 2048) >> 3; c = id & 7; gb = Gbase; soff = 32768; }
                else                { row = (id - 3072) >> 3; c = id & 7; gb = Ubase; soff = 49152; }
                soff += row * 128 + (((uint32_t)c ^ (row & 7)) << 4);
                cp16s(st + soff, gb + (size_t)row * K + koff + c * 8);
            }
        }
        CP_COMMIT();
        asm volatile("cp.async.wait_group 2;");
        __syncthreads();

        int cur = ldst + 1; if (cur >= 3) cur -= 3;
        const uint32_t st = sbase + cur * GU_STAGE;
        const uint32_t swz = lane & 7;
        #pragma unroll
        for (int ks = 0; ks < 4; ks++) {
            uint32_t a[4][4], bg[4][2], bu[4][2];
            #pragma unroll
            for (int mi = 0; mi < 4; mi++) {
                int row = wm + mi * 16 + (lane & 15);
                uint32_t ch = ((uint32_t)(2 * ks + (lane >> 4))) ^ swz;
                ldsm4(a[mi], st + row * 128 + (ch << 4));
            }
            #pragma unroll
            for (int ni = 0; ni < 4; ni += 2) {
                int row = wn + ni * 8 + ((lane >> 4) << 3) + (lane & 7);
                uint32_t ch = ((uint32_t)(2 * ks + ((lane >> 3) & 1))) ^ swz;
                uint32_t r4[4];
                ldsm4(r4, st + 32768 + row * 128 + (ch << 4));
                bg[ni][0] = r4[0]; bg[ni][1] = r4[1];
                bg[ni+1][0] = r4[2]; bg[ni+1][1] = r4[3];
                ldsm4(r4, st + 49152 + row * 128 + (ch << 4));
                bu[ni][0] = r4[0]; bu[ni][1] = r4[1];
                bu[ni+1][0] = r4[2]; bu[ni+1][1] = r4[3];
            }
            #pragma unroll
            for (int mi = 0; mi < 4; mi++)
                #pragma unroll
                for (int ni = 0; ni < 4; ni++) {
                    hmma(accg[mi][ni], a[mi], bg[ni]);
                    hmma(accu[mi][ni], a[mi], bu[ni]);
                }
        }
        __syncthreads();
        if (++ldst >= 3) ldst = 0;
    }

    // epilogue: half(gelu(g) * u)
    #pragma unroll
    for (int mi = 0; mi < 4; mi++) {
        #pragma unroll
        for (int ni = 0; ni < 4; ni++) {
            int r0 = m0 + wm + mi * 16 + (lane >> 2);
            int col = n0 + wn + ni * 8 + ((lane & 3) << 1);
            size_t i0 = (size_t)r0 * INTER + col;
            size_t i1 = i0 + (size_t)8 * INTER;
            float* gg = accg[mi][ni];
            float* uu = accu[mi][ni];
            *(__half2*)(OH + i0) = __floats2half2_rn(gelu_tanh(gg[0]) * uu[0],
                                                     gelu_tanh(gg[1]) * uu[1]);
            *(__half2*)(OH + i1) = __floats2half2_rn(gelu_tanh(gg[2]) * uu[2],
                                                     gelu_tanh(gg[3]) * uu[3]);
        }
    }
}

// ---------------- attention: one block per (b,h), RoPE fused on load ----------------
#define ATTN_SMEM ((64*260 + 256*66 + 64*256 + 64*68) * 4)
__global__ __launch_bounds__(256) void attn_kernel(
    const __half* __restrict__ q, const __half* __restrict__ k, const __half* __restrict__ v,
    const float* __restrict__ mask, const int* __restrict__ pos_ids,
    const float* __restrict__ invf,
    float* __restrict__ attn_out, __half* __restrict__ ao)
{
    extern __shared__ float sm[];
    float* Qs = sm;                     // [64][260]
    float* Ks = Qs + 64 * 260;          // [256][66]
    float* Vs = Ks + 256 * 66;          // [64][256]
    float* AS = Vs + 64 * 256;          // [64][68]
    int h = blockIdx.x, b = blockIdx.y;
    int tid = threadIdx.x;
    const __half* qb = q + ((size_t)b * SDIM * HHE + h) * HD;
    const __half* kb = k + (size_t)b * SDIM * HD;
    const __half* vb = v + (size_t)b * SDIM * HD;
    for (int i = tid; i < 64 * 128; i += 256) {
        int r = i >> 7, d = i & 127;
        float p = (float)pos_ids[r * SDIM + b];
        float ang = p * invf[d];
        float c = cosf(ang), sn = sinf(ang);
        float q1 = __half2float(qb[(size_t)r * (HHE*HD) + d]);
        float q2 = __half2float(qb[(size_t)r * (HHE*HD) + d + 128]);
        Qs[r * 260 + d]       = q1 * c - q2 * sn;
        Qs[r * 260 + d + 128] = q2 * c + q1 * sn;
        float k1 = __half2float(kb[r * HD + d]);
        float k2 = __half2float(kb[r * HD + d + 128]);
        Ks[d * 66 + r]         = k1 * c - k2 * sn;
        Ks[(d + 128) * 66 + r] = k2 * c + k1 * sn;
    }
    for (int i = tid; i < 64 * 256; i += 256) Vs[i] = __half2float(vb[i]);
    __syncthreads();

    int qi = tid >> 2, part = tid & 3;
    float sc[16];
    #pragma unroll
    for (int j = 0; j < 16; j++) sc[j] = 0.f;
    const float* qrow = Qs + qi * 260;
    #pragma unroll 4
    for (int d = 0; d < 256; d++) {
        float qd = qrow[d];
        const float* kd = Ks + d * 66 + part;
        #pragma unroll
        for (int j = 0; j < 16; j++) sc[j] += qd * kd[4 * j];
    }
    const float* mrow = mask + ((size_t)b * 64 + qi) * 64;
    float sf[16];
    float mx = -INFINITY;
    #pragma unroll
    for (int j = 0; j < 16; j++) {
        int kj = part + 4 * j;
        float s = sc[j] * 0.0625f + mrow[kj];
        sf[j] = __half2float(__float2half(s));       // -1e9 -> -inf in f16
        mx = fmaxf(mx, sf[j]);
    }
    mx = fmaxf(mx, __shfl_xor_sync(0xffffffffu, mx, 1));
    mx = fmaxf(mx, __shfl_xor_sync(0xffffffffu, mx, 2));
    float sum = 0.f;
    #pragma unroll
    for (int j = 0; j < 16; j++) {
        float dd = __half2float(__float2half(sf[j] - mx));
        float e  = __half2float(__float2half(expf(dd)));
        sf[j] = e; sum += e;
    }
    sum += __shfl_xor_sync(0xffffffffu, sum, 1);
    sum += __shfl_xor_sync(0xffffffffu, sum, 2);
    float* asr = AS + qi * 68;
    float* aout = attn_out ? attn_out + (((size_t)b * HHE + h) * 64 + qi) * 64 : nullptr;
    #pragma unroll
    for (int j = 0; j < 16; j++) {
        int kj = part + 4 * j;
        float a = __half2float(__float2half(sf[j] / sum));
        asr[kj] = a;
        if (aout) aout[kj] = a;
    }
    __syncthreads();

    float acc[64];
    #pragma unroll
    for (int d2 = 0; d2 < 64; d2++) acc[d2] = 0.f;
    for (int kj = 0; kj < 64; kj++) {
        float av = asr[kj];
        const float* vr = Vs + kj * 256 + part;
        #pragma unroll
        for (int d2 = 0; d2 < 64; d2++) acc[d2] += av * vr[4 * d2];
    }
    __half* aorow = ao + (((size_t)b * 64 + qi) * HHE + h) * HD + part;
    #pragma unroll
    for (int d2 = 0; d2 < 64; d2++) aorow[4 * d2] = __float2half_rn(acc[d2]);
}

// ---------------- launch ----------------
extern "C" void kernel_launch(void* const* d_in, const int* in_sizes, int n_in,
                              void* d_out, int out_size) {
    const float* x      = (const float*)d_in[0];
    const float* mask   = (const float*)d_in[1];
    const int*   pos    = (const int*)  d_in[2];
    const float* invf   = (const float*)d_in[3];
    const float* wq     = (const float*)d_in[4];
    const float* wk     = (const float*)d_in[5];
    const float* wv     = (const float*)d_in[6];
    const float* wo     = (const float*)d_in[7];
    const float* wgate  = (const float*)d_in[8];
    const float* wup    = (const float*)d_in[9];
    const float* wdown  = (const float*)d_in[10];
    const float* ln1    = (const float*)d_in[11];
    const float* ln2    = (const float*)d_in[12];

    float* out = (float*)d_out;
    float* out_h = out;
    const int HID_N = ROWS * DDIM;
    const int ATT_N = BDIM * HHE * SDIM * SDIM;
    float* out_attn = (out_size >= HID_N + ATT_N) ? out + HID_N : nullptr;

    __half *h1h, *qh, *kh, *vh, *aoh, *mlph, *wqh, *wkh, *wvh, *woh, *wgh, *wuh, *wdh;
    cudaGetSymbolAddress((void**)&h1h,  g_h1h);
    cudaGetSymbolAddress((void**)&qh,   g_qh);
    cudaGetSymbolAddress((void**)&kh,   g_kh);
    cudaGetSymbolAddress((void**)&vh,   g_vh);
    cudaGetSymbolAddress((void**)&aoh,  g_aoh);
    cudaGetSymbolAddress((void**)&mlph, g_mlph);
    cudaGetSymbolAddress((void**)&wqh,  g_wqh);
    cudaGetSymbolAddress((void**)&wkh,  g_wkh);
    cudaGetSymbolAddress((void**)&wvh,  g_wvh);
    cudaGetSymbolAddress((void**)&woh,  g_woh);
    cudaGetSymbolAddress((void**)&wgh,  g_wgh);
    cudaGetSymbolAddress((void**)&wuh,  g_wuh);
    cudaGetSymbolAddress((void**)&wdh,  g_wdh);

    cudaFuncSetAttribute(attn_kernel, cudaFuncAttributeMaxDynamicSharedMemorySize, ATTN_SMEM);
    cudaFuncSetAttribute(gemm_h, cudaFuncAttributeMaxDynamicSharedMemorySize, GEMM_SMEM);
    cudaFuncSetAttribute(gemm_gateup, cudaFuncAttributeMaxDynamicSharedMemorySize, GU_SMEM);

    auto cv = [](const float* src, __half* dst, size_t n) {
        int n8 = (int)(n / 8);
        cvt_h_kernel<<<(n8 + 255) / 256, 256>>>((const float4*)src, (half2x4*)dst, n8);
    };

    // weight converts
    cv(wq, wqh, (size_t)DDIM*DDIM);
    cv(wk, wkh, (size_t)HD*DDIM);
    cv(wv, wvh, (size_t)HD*DDIM);
    cv(wo, woh, (size_t)DDIM*DDIM);
    // rmsnorm 1 -> fp16
    rmsnorm_kernel<<<ROWS, 256>>>(x, ln1, (__half2*)h1h);
    // Q projection -> fp16
    gemm_h<<<dim3(ROWS/256, DDIM/256), 512, GEMM_SMEM>>>(h1h, wqh, nullptr, nullptr,
                                                         nullptr, qh, nullptr, DDIM, DDIM, 3);
    // K+V fused -> fp16 (N = HD = 256, one n-tile)
    gemm_h<<<dim3(ROWS/256, 1, 2), 512, GEMM_SMEM>>>(h1h, wkh, wvh, nullptr,
                                                     nullptr, kh, vh, HD, DDIM, 3);
    // attention (RoPE fused; fp32 probs to out, fp16 context to aoh)
    attn_kernel<<<dim3(HHE, BDIM), 256, ATTN_SMEM>>>(qh, kh, vh, mask, pos, invf, out_attn, aoh);
    // O projection + residual -> out_h
    gemm_h<<<dim3(ROWS/256, DDIM/256), 512, GEMM_SMEM>>>(aoh, woh, nullptr, out_h,
                                                         x, nullptr, nullptr, DDIM, DDIM, 1);
    // rmsnorm 2 -> fp16
    rmsnorm_kernel<<<ROWS, 256>>>(out_h, ln2, (__half2*)h1h);
    // mlp weight converts
    cv(wgate, wgh, (size_t)INTER*DDIM);
    cv(wup,   wuh, (size_t)INTER*DDIM);
    cv(wdown, wdh, (size_t)DDIM*INTER);
    // fused gate+up GEMM with gelu-mul epilogue -> fp16 mlph
    gemm_gateup<<<dim3(ROWS/256, INTER/128), 512, GU_SMEM>>>(h1h, wgh, wuh, mlph, DDIM);
    // down projection + residual -> out_h
    gemm_h<<<dim3(ROWS/256, DDIM/256), 512, GEMM_SMEM>>>(mlph, wdh, nullptr, out_h,
                                                         out_h, nullptr, nullptr, DDIM, INTER, 1);
}

// round 15
// speedup vs baseline: 2.8684x; 2.8684x over previous
#include <cuda_runtime.h>
#include <cuda_fp16.h>
#include <cstdint>
#include <cstddef>

// ---------------- problem dims ----------------
#define BDIM 64
#define SDIM 64
#define DDIM 2048
#define HHE  8
#define HD   256
#define INTER 16384
#define ROWS (BDIM*SDIM)            // 4096

// ---------------- scratch (device globals; no allocs allowed) ----------------
__device__ __align__(256) __half g_h1h [ROWS*DDIM];
__device__ __align__(256) __half g_qh  [ROWS*DDIM];
__device__ __align__(256) __half g_kh  [ROWS*HD];
__device__ __align__(256) __half g_vh  [ROWS*HD];
__device__ __align__(256) __half g_aoh [ROWS*DDIM];
__device__ __align__(256) __half g_mlph[(size_t)ROWS*INTER];
// fp16 weight copies
__device__ __align__(256) __half g_wqh[DDIM*DDIM];
__device__ __align__(256) __half g_wkh[HD*DDIM];
__device__ __align__(256) __half g_wvh[HD*DDIM];
__device__ __align__(256) __half g_woh[DDIM*DDIM];
__device__ __align__(256) __half g_wgh[(size_t)INTER*DDIM];
__device__ __align__(256) __half g_wuh[(size_t)INTER*DDIM];
__device__ __align__(256) __half g_wdh[(size_t)DDIM*INTER];

struct __align__(16) half2x4 { __half2 a, b, c, d; };

// ---------------- helpers ----------------
__device__ __forceinline__ void cp16s(uint32_t saddr, const void* gsrc) {
    asm volatile("cp.async.cg.shared.global [%0], [%1], 16;" :: "r"(saddr), "l"(gsrc));
}
#define CP_COMMIT() asm volatile("cp.async.commit_group;")

__device__ __forceinline__ void ldsm4(uint32_t* r, uint32_t a) {
    asm volatile("ldmatrix.sync.aligned.m8n8.x4.shared.b16 {%0,%1,%2,%3}, [%4];"
                 : "=r"(r[0]), "=r"(r[1]), "=r"(r[2]), "=r"(r[3]) : "r"(a));
}
__device__ __forceinline__ void hmma(float* c, const uint32_t* a, const uint32_t* b) {
    asm volatile("mma.sync.aligned.m16n8k16.row.col.f32.f16.f16.f32 "
                 "{%0,%1,%2,%3}, {%4,%5,%6,%7}, {%8,%9}, {%0,%1,%2,%3};"
                 : "+f"(c[0]), "+f"(c[1]), "+f"(c[2]), "+f"(c[3])
                 : "r"(a[0]), "r"(a[1]), "r"(a[2]), "r"(a[3]), "r"(b[0]), "r"(b[1]));
}
__device__ __forceinline__ float gelu_tanh(float x) {
    float t = tanhf(0.7978845608028654f * (x + 0.044715f * x * x * x));
    return 0.5f * x * (1.0f + t);
}

// ---------------- fp32 -> fp16 convert (8 elems/thread) ----------------
__global__ void cvt_h_kernel(const float4* __restrict__ in, half2x4* __restrict__ out, int n8) {
    int i = blockIdx.x * blockDim.x + threadIdx.x;
    if (i >= n8) return;
    float4 v0 = in[2*i], v1 = in[2*i+1];
    half2x4 o;
    o.a = __floats2half2_rn(v0.x, v0.y);
    o.b = __floats2half2_rn(v0.z, v0.w);
    o.c = __floats2half2_rn(v1.x, v1.y);
    o.d = __floats2half2_rn(v1.z, v1.w);
    out[i] = o;
}

// ---------------- rmsnorm (fp16 output for GEMM consumption) ----------------
__global__ __launch_bounds__(256) void rmsnorm_kernel(const float* __restrict__ x,
                                                      const float* __restrict__ w,
                                                      __half2* __restrict__ out) {
    int row = blockIdx.x;
    const float4* x4 = (const float4*)(x + (size_t)row * DDIM);
    const float4* w4 = (const float4*)w;
    __half2* o2 = out + (size_t)row * (DDIM/2);
    int t = threadIdx.x;
    float4 a = x4[t], b = x4[t + 256];
    float s = a.x*a.x + a.y*a.y + a.z*a.z + a.w*a.w
            + b.x*b.x + b.y*b.y + b.z*b.z + b.w*b.w;
    #pragma unroll
    for (int o = 16; o > 0; o >>= 1) s += __shfl_xor_sync(0xffffffffu, s, o);
    __shared__ float red[8];
    if ((t & 31) == 0) red[t >> 5] = s;
    __syncthreads();
    float tot = 0.f;
    #pragma unroll
    for (int i = 0; i < 8; i++) tot += red[i];
    float r = rsqrtf(tot * (1.0f / DDIM) + 1e-6f);
    float4 wa = w4[t], wb = w4[t + 256];
    o2[2*t]          = __floats2half2_rn(a.x*r*(1.f+wa.x), a.y*r*(1.f+wa.y));
    o2[2*t+1]        = __floats2half2_rn(a.z*r*(1.f+wa.z), a.w*r*(1.f+wa.w));
    o2[512 + 2*t]    = __floats2half2_rn(b.x*r*(1.f+wb.x), b.y*r*(1.f+wb.y));
    o2[512 + 2*t+1]  = __floats2half2_rn(b.z*r*(1.f+wb.z), b.w*r*(1.f+wb.w));
}

// ---------------- fp16 tensor-core GEMM (single-B) ----------------
// C(M,N) = A(M,K:half) @ B(N,K:half)^T
// CTA tile 128x128, 4 warps (64x64 each), BK=64, 3-stage cp.async, 2 CTAs/SM.
// mode 1: C = acc + R (fp32)
// mode 3: OH(x) = half(acc)
// blockIdx.z selects (B2, OH2) operands (fused K/V projections).
#define BKT 64
#define NSTAGE 3
#define STAGE_B ((128 + 128) * BKT * 2)     // 32768
#define GEMM_SMEM (NSTAGE * STAGE_B)        // 98304

__global__ __launch_bounds__(128, 2) void gemm_h(
    const __half* __restrict__ A, const __half* __restrict__ Bw,
    const __half* __restrict__ B2,
    float* __restrict__ C,
    const float* __restrict__ R,
    __half* __restrict__ OH, __half* __restrict__ OH2,
    int N, int K, int mode)
{
    extern __shared__ char smem[];
    const uint32_t sbase = (uint32_t)__cvta_generic_to_shared(smem);
    const int tid = threadIdx.x;
    const int lane = tid & 31, warp = tid >> 5;
    const int m0 = blockIdx.x * 128, n0 = blockIdx.y * 128;
    const __half* Bx = blockIdx.z ? B2 : Bw;
    __half* OHx = blockIdx.z ? OH2 : OH;

    const int wm = (warp & 1) * 64;      // 0 or 64
    const int wn = (warp >> 1) * 64;     // 0 or 64

    const __half* Abase = A + (size_t)m0 * K;
    const __half* Bbase = Bx + (size_t)n0 * K;

    float acc[4][8][4];
    #pragma unroll
    for (int i = 0; i < 4; i++)
        #pragma unroll
        for (int j = 0; j < 8; j++) {
            acc[i][j][0] = 0.f; acc[i][j][1] = 0.f; acc[i][j][2] = 0.f; acc[i][j][3] = 0.f;
        }

    const int KT = K / BKT;
    // 2048 chunks of 16B per stage (A:1024, B:1024), 16 per thread
    #pragma unroll
    for (int p = 0; p < 2; p++) {
        uint32_t st = sbase + p * STAGE_B;
        #pragma unroll
        for (int i = 0; i < 16; i++) {
            int id = tid + (i << 7);
            if (id < 1024) {
                int row = id >> 3, c = id & 7;
                uint32_t soff = row * 128 + (((uint32_t)c ^ (row & 7)) << 4);
                cp16s(st + soff, Abase + (size_t)row * K + p * BKT + c * 8);
            } else {
                int idb = id - 1024;
                int row = idb >> 3, c = idb & 7;
                uint32_t soff = row * 128 + (((uint32_t)c ^ (row & 7)) << 4);
                cp16s(st + 16384 + soff, Bbase + (size_t)row * K + p * BKT + c * 8);
            }
        }
        CP_COMMIT();
    }

    int ldst = 2;   // stage index to load next
    for (int kt = 0; kt < KT; kt++) {
        if (kt + 2 < KT) {
            uint32_t st = sbase + ldst * STAGE_B;
            int koff = (kt + 2) * BKT;
            #pragma unroll
            for (int i = 0; i < 16; i++) {
                int id = tid + (i << 7);
                if (id < 1024) {
                    int row = id >> 3, c = id & 7;
                    uint32_t soff = row * 128 + (((uint32_t)c ^ (row & 7)) << 4);
                    cp16s(st + soff, Abase + (size_t)row * K + koff + c * 8);
                } else {
                    int idb = id - 1024;
                    int row = idb >> 3, c = idb & 7;
                    uint32_t soff = row * 128 + (((uint32_t)c ^ (row & 7)) << 4);
                    cp16s(st + 16384 + soff, Bbase + (size_t)row * K + koff + c * 8);
                }
            }
        }
        CP_COMMIT();
        asm volatile("cp.async.wait_group 2;");
        __syncthreads();

        int cur = ldst + 1; if (cur >= NSTAGE) cur -= NSTAGE;   // == kt % 3
        const uint32_t st = sbase + cur * STAGE_B;
        const uint32_t swz = lane & 7;
        #pragma unroll
        for (int ks = 0; ks < 4; ks++) {
            uint32_t a[4][4], b[8][2];
            #pragma unroll
            for (int mi = 0; mi < 4; mi++) {
                int row = wm + mi * 16 + (lane & 15);
                uint32_t ch = ((uint32_t)(2 * ks + (lane >> 4))) ^ swz;
                ldsm4(a[mi], st + row * 128 + (ch << 4));
            }
            #pragma unroll
            for (int ni = 0; ni < 8; ni += 2) {
                int row = wn + ni * 8 + ((lane >> 4) << 3) + (lane & 7);
                uint32_t ch = ((uint32_t)(2 * ks + ((lane >> 3) & 1))) ^ swz;
                uint32_t r4[4];
                ldsm4(r4, st + 16384 + row * 128 + (ch << 4));
                b[ni][0] = r4[0]; b[ni][1] = r4[1];
                b[ni+1][0] = r4[2]; b[ni+1][1] = r4[3];
            }
            #pragma unroll
            for (int mi = 0; mi < 4; mi++)
                #pragma unroll
                for (int ni = 0; ni < 8; ni++)
                    hmma(acc[mi][ni], a[mi], b[ni]);
        }
        __syncthreads();
        if (++ldst >= NSTAGE) ldst = 0;
    }

    // epilogue
    #pragma unroll
    for (int mi = 0; mi < 4; mi++) {
        #pragma unroll
        for (int ni = 0; ni < 8; ni++) {
            int r0 = m0 + wm + mi * 16 + (lane >> 2);
            int col = n0 + wn + ni * 8 + ((lane & 3) << 1);
            size_t i0 = (size_t)r0 * N + col;
            size_t i1 = i0 + (size_t)8 * N;
            float* cc = acc[mi][ni];
            if (mode == 1) {
                float2 r0v = *(const float2*)(R + i0);
                float2 r1v = *(const float2*)(R + i1);
                *(float2*)(C + i0) = make_float2(cc[0] + r0v.x, cc[1] + r0v.y);
                *(float2*)(C + i1) = make_float2(cc[2] + r1v.x, cc[3] + r1v.y);
            } else {
                *(__half2*)(OHx + i0) = __floats2half2_rn(cc[0], cc[1]);
                *(__half2*)(OHx + i1) = __floats2half2_rn(cc[2], cc[3]);
            }
        }
    }
}

// ---------------- fused gate+up GEMM with gelu-mul epilogue ----------------
// CTA tile 128(M) x 128(N), dual-B, 256 threads, 8 warps (64x32 each, 2x4),
// BK=64, 4-stage cp.async. (round-11 proven config)
#define GU_STAGE ((128 + 128 + 128) * BKT * 2)   // 49152
#define GU_SMEM (4 * GU_STAGE)                   // 196608

__global__ __launch_bounds__(256, 1) void gemm_gateup(
    const __half* __restrict__ A, const __half* __restrict__ Bg,
    const __half* __restrict__ Bu, __half* __restrict__ OH, int K)
{
    extern __shared__ char smem[];
    const uint32_t sbase = (uint32_t)__cvta_generic_to_shared(smem);
    const int tid = threadIdx.x;
    const int lane = tid & 31, warp = tid >> 5;
    const int m0 = blockIdx.x * 128, n0 = blockIdx.y * 128;

    const int wm = (warp & 1) * 64;      // 0 or 64
    const int wn = (warp >> 1) * 32;     // 0,32,64,96

    const __half* Abase = A + (size_t)m0 * K;
    const __half* Gbase = Bg + (size_t)n0 * K;
    const __half* Ubase = Bu + (size_t)n0 * K;

    float accg[4][4][4], accu[4][4][4];
    #pragma unroll
    for (int i = 0; i < 4; i++)
        #pragma unroll
        for (int j = 0; j < 4; j++)
            #pragma unroll
            for (int c = 0; c < 4; c++) { accg[i][j][c] = 0.f; accu[i][j][c] = 0.f; }

    const int KT = K / BKT;
    // 3072 chunks/stage: A 0..1023, Bg 1024..2047, Bu 2048..3071; 12 per thread
    #pragma unroll
    for (int p = 0; p < 3; p++) {
        uint32_t st = sbase + p * GU_STAGE;
        #pragma unroll
        for (int i = 0; i < 12; i++) {
            int id = tid + (i << 8);
            int sel = id >> 10;           // 0=A,1=Bg,2=Bu
            int idl = id & 1023;
            int row = idl >> 3, c = idl & 7;
            uint32_t soff = (uint32_t)sel * 16384 + row * 128 + (((uint32_t)c ^ (row & 7)) << 4);
            const __half* gb = (sel == 0 ? Abase : (sel == 1 ? Gbase : Ubase));
            cp16s(st + soff, gb + (size_t)row * K + p * BKT + c * 8);
        }
        CP_COMMIT();
    }

    for (int kt = 0; kt < KT; kt++) {
        if (kt + 3 < KT) {
            uint32_t st = sbase + ((kt + 3) & 3) * GU_STAGE;
            int koff = (kt + 3) * BKT;
            #pragma unroll
            for (int i = 0; i < 12; i++) {
                int id = tid + (i << 8);
                int sel = id >> 10;
                int idl = id & 1023;
                int row = idl >> 3, c = idl & 7;
                uint32_t soff = (uint32_t)sel * 16384 + row * 128 + (((uint32_t)c ^ (row & 7)) << 4);
                const __half* gb = (sel == 0 ? Abase : (sel == 1 ? Gbase : Ubase));
                cp16s(st + soff, gb + (size_t)row * K + koff + c * 8);
            }
        }
        CP_COMMIT();
        asm volatile("cp.async.wait_group 3;");
        __syncthreads();

        const uint32_t st = sbase + (kt & 3) * GU_STAGE;
        const uint32_t swz = lane & 7;
        #pragma unroll
        for (int ks = 0; ks < 4; ks++) {
            uint32_t a[4][4], bg[4][2], bu[4][2];
            #pragma unroll
            for (int mi = 0; mi < 4; mi++) {
                int row = wm + mi * 16 + (lane & 15);
                uint32_t ch = ((uint32_t)(2 * ks + (lane >> 4))) ^ swz;
                ldsm4(a[mi], st + row * 128 + (ch << 4));
            }
            #pragma unroll
            for (int ni = 0; ni < 4; ni += 2) {
                int row = wn + ni * 8 + ((lane >> 4) << 3) + (lane & 7);
                uint32_t ch = ((uint32_t)(2 * ks + ((lane >> 3) & 1))) ^ swz;
                uint32_t r4[4];
                ldsm4(r4, st + 16384 + row * 128 + (ch << 4));
                bg[ni][0] = r4[0]; bg[ni][1] = r4[1];
                bg[ni+1][0] = r4[2]; bg[ni+1][1] = r4[3];
                ldsm4(r4, st + 32768 + row * 128 + (ch << 4));
                bu[ni][0] = r4[0]; bu[ni][1] = r4[1];
                bu[ni+1][0] = r4[2]; bu[ni+1][1] = r4[3];
            }
            #pragma unroll
            for (int mi = 0; mi < 4; mi++)
                #pragma unroll
                for (int ni = 0; ni < 4; ni++) {
                    hmma(accg[mi][ni], a[mi], bg[ni]);
                    hmma(accu[mi][ni], a[mi], bu[ni]);
                }
        }
        __syncthreads();
    }

    // epilogue: half(gelu(g) * u)
    #pragma unroll
    for (int mi = 0; mi < 4; mi++) {
        #pragma unroll
        for (int ni = 0; ni < 4; ni++) {
            int r0 = m0 + wm + mi * 16 + (lane >> 2);
            int col = n0 + wn + ni * 8 + ((lane & 3) << 1);
            size_t i0 = (size_t)r0 * INTER + col;
            size_t i1 = i0 + (size_t)8 * INTER;
            float* gg = accg[mi][ni];
            float* uu = accu[mi][ni];
            *(__half2*)(OH + i0) = __floats2half2_rn(gelu_tanh(gg[0]) * uu[0],
                                                     gelu_tanh(gg[1]) * uu[1]);
            *(__half2*)(OH + i1) = __floats2half2_rn(gelu_tanh(gg[2]) * uu[2],
                                                     gelu_tanh(gg[3]) * uu[3]);
        }
    }
}

// ---------------- attention: one block per (b,h), RoPE fused on load ----------------
#define ATTN_SMEM ((64*260 + 256*66 + 64*256 + 64*68) * 4)
__global__ __launch_bounds__(256) void attn_kernel(
    const __half* __restrict__ q, const __half* __restrict__ k, const __half* __restrict__ v,
    const float* __restrict__ mask, const int* __restrict__ pos_ids,
    const float* __restrict__ invf,
    float* __restrict__ attn_out, __half* __restrict__ ao)
{
    extern __shared__ float sm[];
    float* Qs = sm;                     // [64][260]
    float* Ks = Qs + 64 * 260;          // [256][66]
    float* Vs = Ks + 256 * 66;          // [64][256]
    float* AS = Vs + 64 * 256;          // [64][68]
    int h = blockIdx.x, b = blockIdx.y;
    int tid = threadIdx.x;
    const __half* qb = q + ((size_t)b * SDIM * HHE + h) * HD;
    const __half* kb = k + (size_t)b * SDIM * HD;
    const __half* vb = v + (size_t)b * SDIM * HD;
    for (int i = tid; i < 64 * 128; i += 256) {
        int r = i >> 7, d = i & 127;
        float p = (float)pos_ids[r * SDIM + b];
        float ang = p * invf[d];
        float c = cosf(ang), sn = sinf(ang);
        float q1 = __half2float(qb[(size_t)r * (HHE*HD) + d]);
        float q2 = __half2float(qb[(size_t)r * (HHE*HD) + d + 128]);
        Qs[r * 260 + d]       = q1 * c - q2 * sn;
        Qs[r * 260 + d + 128] = q2 * c + q1 * sn;
        float k1 = __half2float(kb[r * HD + d]);
        float k2 = __half2float(kb[r * HD + d + 128]);
        Ks[d * 66 + r]         = k1 * c - k2 * sn;
        Ks[(d + 128) * 66 + r] = k2 * c + k1 * sn;
    }
    for (int i = tid; i < 64 * 256; i += 256) Vs[i] = __half2float(vb[i]);
    __syncthreads();

    int qi = tid >> 2, part = tid & 3;
    float sc[16];
    #pragma unroll
    for (int j = 0; j < 16; j++) sc[j] = 0.f;
    const float* qrow = Qs + qi * 260;
    #pragma unroll 4
    for (int d = 0; d < 256; d++) {
        float qd = qrow[d];
        const float* kd = Ks + d * 66 + part;
        #pragma unroll
        for (int j = 0; j < 16; j++) sc[j] += qd * kd[4 * j];
    }
    const float* mrow = mask + ((size_t)b * 64 + qi) * 64;
    float sf[16];
    float mx = -INFINITY;
    #pragma unroll
    for (int j = 0; j < 16; j++) {
        int kj = part + 4 * j;
        float s = sc[j] * 0.0625f + mrow[kj];
        sf[j] = __half2float(__float2half(s));       // -1e9 -> -inf in f16
        mx = fmaxf(mx, sf[j]);
    }
    mx = fmaxf(mx, __shfl_xor_sync(0xffffffffu, mx, 1));
    mx = fmaxf(mx, __shfl_xor_sync(0xffffffffu, mx, 2));
    float sum = 0.f;
    #pragma unroll
    for (int j = 0; j < 16; j++) {
        float dd = __half2float(__float2half(sf[j] - mx));
        float e  = __half2float(__float2half(expf(dd)));
        sf[j] = e; sum += e;
    }
    sum += __shfl_xor_sync(0xffffffffu, sum, 1);
    sum += __shfl_xor_sync(0xffffffffu, sum, 2);
    float* asr = AS + qi * 68;
    float* aout = attn_out ? attn_out + (((size_t)b * HHE + h) * 64 + qi) * 64 : nullptr;
    #pragma unroll
    for (int j = 0; j < 16; j++) {
        int kj = part + 4 * j;
        float a = __half2float(__float2half(sf[j] / sum));
        asr[kj] = a;
        if (aout) aout[kj] = a;
    }
    __syncthreads();

    float acc[64];
    #pragma unroll
    for (int d2 = 0; d2 < 64; d2++) acc[d2] = 0.f;
    for (int kj = 0; kj < 64; kj++) {
        float av = asr[kj];
        const float* vr = Vs + kj * 256 + part;
        #pragma unroll
        for (int d2 = 0; d2 < 64; d2++) acc[d2] += av * vr[4 * d2];
    }
    __half* aorow = ao + (((size_t)b * 64 + qi) * HHE + h) * HD + part;
    #pragma unroll
    for (int d2 = 0; d2 < 64; d2++) aorow[4 * d2] = __float2half_rn(acc[d2]);
}

// ---------------- launch ----------------
extern "C" void kernel_launch(void* const* d_in, const int* in_sizes, int n_in,
                              void* d_out, int out_size) {
    const float* x      = (const float*)d_in[0];
    const float* mask   = (const float*)d_in[1];
    const int*   pos    = (const int*)  d_in[2];
    const float* invf   = (const float*)d_in[3];
    const float* wq     = (const float*)d_in[4];
    const float* wk     = (const float*)d_in[5];
    const float* wv     = (const float*)d_in[6];
    const float* wo     = (const float*)d_in[7];
    const float* wgate  = (const float*)d_in[8];
    const float* wup    = (const float*)d_in[9];
    const float* wdown  = (const float*)d_in[10];
    const float* ln1    = (const float*)d_in[11];
    const float* ln2    = (const float*)d_in[12];

    float* out = (float*)d_out;
    float* out_h = out;
    const int HID_N = ROWS * DDIM;
    const int ATT_N = BDIM * HHE * SDIM * SDIM;
    float* out_attn = (out_size >= HID_N + ATT_N) ? out + HID_N : nullptr;

    __half *h1h, *qh, *kh, *vh, *aoh, *mlph, *wqh, *wkh, *wvh, *woh, *wgh, *wuh, *wdh;
    cudaGetSymbolAddress((void**)&h1h,  g_h1h);
    cudaGetSymbolAddress((void**)&qh,   g_qh);
    cudaGetSymbolAddress((void**)&kh,   g_kh);
    cudaGetSymbolAddress((void**)&vh,   g_vh);
    cudaGetSymbolAddress((void**)&aoh,  g_aoh);
    cudaGetSymbolAddress((void**)&mlph, g_mlph);
    cudaGetSymbolAddress((void**)&wqh,  g_wqh);
    cudaGetSymbolAddress((void**)&wkh,  g_wkh);
    cudaGetSymbolAddress((void**)&wvh,  g_wvh);
    cudaGetSymbolAddress((void**)&woh,  g_woh);
    cudaGetSymbolAddress((void**)&wgh,  g_wgh);
    cudaGetSymbolAddress((void**)&wuh,  g_wuh);
    cudaGetSymbolAddress((void**)&wdh,  g_wdh);

    cudaFuncSetAttribute(attn_kernel, cudaFuncAttributeMaxDynamicSharedMemorySize, ATTN_SMEM);
    cudaFuncSetAttribute(gemm_h, cudaFuncAttributeMaxDynamicSharedMemorySize, GEMM_SMEM);
    cudaFuncSetAttribute(gemm_gateup, cudaFuncAttributeMaxDynamicSharedMemorySize, GU_SMEM);

    auto cv = [](const float* src, __half* dst, size_t n) {
        int n8 = (int)(n / 8);
        cvt_h_kernel<<<(n8 + 255) / 256, 256>>>((const float4*)src, (half2x4*)dst, n8);
    };

    // weight converts
    cv(wq, wqh, (size_t)DDIM*DDIM);
    cv(wk, wkh, (size_t)HD*DDIM);
    cv(wv, wvh, (size_t)HD*DDIM);
    cv(wo, woh, (size_t)DDIM*DDIM);
    // rmsnorm 1 -> fp16
    rmsnorm_kernel<<<ROWS, 256>>>(x, ln1, (__half2*)h1h);
    // Q projection -> fp16
    gemm_h<<<dim3(ROWS/128, DDIM/128), 128, GEMM_SMEM>>>(h1h, wqh, nullptr, nullptr,
                                                         nullptr, qh, nullptr, DDIM, DDIM, 3);
    // K+V fused -> fp16
    gemm_h<<<dim3(ROWS/128, HD/128, 2), 128, GEMM_SMEM>>>(h1h, wkh, wvh, nullptr,
                                                          nullptr, kh, vh, HD, DDIM, 3);
    // attention (RoPE fused; fp32 probs to out, fp16 context to aoh)
    attn_kernel<<<dim3(HHE, BDIM), 256, ATTN_SMEM>>>(qh, kh, vh, mask, pos, invf, out_attn, aoh);
    // O projection + residual -> out_h
    gemm_h<<<dim3(ROWS/128, DDIM/128), 128, GEMM_SMEM>>>(aoh, woh, nullptr, out_h,
                                                         x, nullptr, nullptr, DDIM, DDIM, 1);
    // rmsnorm 2 -> fp16
    rmsnorm_kernel<<<ROWS, 256>>>(out_h, ln2, (__half2*)h1h);
    // mlp weight converts
    cv(wgate, wgh, (size_t)INTER*DDIM);
    cv(wup,   wuh, (size_t)INTER*DDIM);
    cv(wdown, wdh, (size_t)DDIM*INTER);
    // fused gate+up GEMM (128x128 dual-B) with gelu-mul epilogue -> fp16 mlph
    gemm_gateup<<<dim3(ROWS/128, INTER/128), 256, GU_SMEM>>>(h1h, wgh, wuh, mlph, DDIM);
    // down projection + residual -> out_h
    gemm_h<<<dim3(ROWS/128, DDIM/128), 128, GEMM_SMEM>>>(mlph, wdh, nullptr, out_h,
                                                         out_h, nullptr, nullptr, DDIM, INTER, 1);
}

// round 16
// speedup vs baseline: 2.8870x; 1.0065x over previous
#include <cuda_runtime.h>
#include <cuda_fp16.h>
#include <cstdint>
#include <cstddef>

// ---------------- problem dims ----------------
#define BDIM 64
#define SDIM 64
#define DDIM 2048
#define HHE  8
#define HD   256
#define INTER 16384
#define ROWS (BDIM*SDIM)            // 4096

// ---------------- scratch (device globals; no allocs allowed) ----------------
__device__ __align__(256) __half g_h1h [ROWS*DDIM];
__device__ __align__(256) __half g_qh  [ROWS*DDIM];
__device__ __align__(256) __half g_kh  [ROWS*HD];
__device__ __align__(256) __half g_vh  [ROWS*HD];
__device__ __align__(256) __half g_aoh [ROWS*DDIM];
__device__ __align__(256) __half g_mlph[(size_t)ROWS*INTER];
// fp16 weight copies
__device__ __align__(256) __half g_wqh[DDIM*DDIM];
__device__ __align__(256) __half g_wkh[HD*DDIM];
__device__ __align__(256) __half g_wvh[HD*DDIM];
__device__ __align__(256) __half g_woh[DDIM*DDIM];
__device__ __align__(256) __half g_wgh[(size_t)INTER*DDIM];
__device__ __align__(256) __half g_wuh[(size_t)INTER*DDIM];
__device__ __align__(256) __half g_wdh[(size_t)DDIM*INTER];

struct __align__(16) half2x4 { __half2 a, b, c, d; };

// ---------------- helpers ----------------
__device__ __forceinline__ void cp16s(uint32_t saddr, const void* gsrc) {
    asm volatile("cp.async.cg.shared.global [%0], [%1], 16;" :: "r"(saddr), "l"(gsrc));
}
#define CP_COMMIT() asm volatile("cp.async.commit_group;")

__device__ __forceinline__ void ldsm4(uint32_t* r, uint32_t a) {
    asm volatile("ldmatrix.sync.aligned.m8n8.x4.shared.b16 {%0,%1,%2,%3}, [%4];"
                 : "=r"(r[0]), "=r"(r[1]), "=r"(r[2]), "=r"(r[3]) : "r"(a));
}
__device__ __forceinline__ void hmma(float* c, const uint32_t* a, const uint32_t* b) {
    asm volatile("mma.sync.aligned.m16n8k16.row.col.f32.f16.f16.f32 "
                 "{%0,%1,%2,%3}, {%4,%5,%6,%7}, {%8,%9}, {%0,%1,%2,%3};"
                 : "+f"(c[0]), "+f"(c[1]), "+f"(c[2]), "+f"(c[3])
                 : "r"(a[0]), "r"(a[1]), "r"(a[2]), "r"(a[3]), "r"(b[0]), "r"(b[1]));
}
__device__ __forceinline__ float gelu_tanh(float x) {
    float t = tanhf(0.7978845608028654f * (x + 0.044715f * x * x * x));
    return 0.5f * x * (1.0f + t);
}

// ---------------- fp32 -> fp16 convert (8 elems/thread) ----------------
__global__ void cvt_h_kernel(const float4* __restrict__ in, half2x4* __restrict__ out, int n8) {
    int i = blockIdx.x * blockDim.x + threadIdx.x;
    if (i >= n8) return;
    float4 v0 = in[2*i], v1 = in[2*i+1];
    half2x4 o;
    o.a = __floats2half2_rn(v0.x, v0.y);
    o.b = __floats2half2_rn(v0.z, v0.w);
    o.c = __floats2half2_rn(v1.x, v1.y);
    o.d = __floats2half2_rn(v1.z, v1.w);
    out[i] = o;
}

// ---------------- rmsnorm (fp16 output for GEMM consumption) ----------------
__global__ __launch_bounds__(256) void rmsnorm_kernel(const float* __restrict__ x,
                                                      const float* __restrict__ w,
                                                      __half2* __restrict__ out) {
    int row = blockIdx.x;
    const float4* x4 = (const float4*)(x + (size_t)row * DDIM);
    const float4* w4 = (const float4*)w;
    __half2* o2 = out + (size_t)row * (DDIM/2);
    int t = threadIdx.x;
    float4 a = x4[t], b = x4[t + 256];
    float s = a.x*a.x + a.y*a.y + a.z*a.z + a.w*a.w
            + b.x*b.x + b.y*b.y + b.z*b.z + b.w*b.w;
    #pragma unroll
    for (int o = 16; o > 0; o >>= 1) s += __shfl_xor_sync(0xffffffffu, s, o);
    __shared__ float red[8];
    if ((t & 31) == 0) red[t >> 5] = s;
    __syncthreads();
    float tot = 0.f;
    #pragma unroll
    for (int i = 0; i < 8; i++) tot += red[i];
    float r = rsqrtf(tot * (1.0f / DDIM) + 1e-6f);
    float4 wa = w4[t], wb = w4[t + 256];
    o2[2*t]          = __floats2half2_rn(a.x*r*(1.f+wa.x), a.y*r*(1.f+wa.y));
    o2[2*t+1]        = __floats2half2_rn(a.z*r*(1.f+wa.z), a.w*r*(1.f+wa.w));
    o2[512 + 2*t]    = __floats2half2_rn(b.x*r*(1.f+wb.x), b.y*r*(1.f+wb.y));
    o2[512 + 2*t+1]  = __floats2half2_rn(b.z*r*(1.f+wb.z), b.w*r*(1.f+wb.w));
}

// ---------------- fp16 tensor-core GEMM (single-B) ----------------
// C(M,N) = A(M,K:half) @ B(N,K:half)^T
// CTA tile 128x128, 4 warps (64x64 each), BK=64, 3-stage cp.async, 2 CTAs/SM.
// mode 1: C = acc + R (fp32)
// mode 3: OH(x) = half(acc)
// blockIdx.z selects (B2, OH2) operands (fused K/V projections).
#define BKT 64
#define NSTAGE 3
#define STAGE_B ((128 + 128) * BKT * 2)     // 32768
#define GEMM_SMEM (NSTAGE * STAGE_B)        // 98304

__global__ __launch_bounds__(128, 2) void gemm_h(
    const __half* __restrict__ A, const __half* __restrict__ Bw,
    const __half* __restrict__ B2,
    float* __restrict__ C,
    const float* __restrict__ R,
    __half* __restrict__ OH, __half* __restrict__ OH2,
    int N, int K, int mode)
{
    extern __shared__ char smem[];
    const uint32_t sbase = (uint32_t)__cvta_generic_to_shared(smem);
    const int tid = threadIdx.x;
    const int lane = tid & 31, warp = tid >> 5;
    const int m0 = blockIdx.x * 128, n0 = blockIdx.y * 128;
    const __half* Bx = blockIdx.z ? B2 : Bw;
    __half* OHx = blockIdx.z ? OH2 : OH;

    const int wm = (warp & 1) * 64;      // 0 or 64
    const int wn = (warp >> 1) * 64;     // 0 or 64

    const __half* Abase = A + (size_t)m0 * K;
    const __half* Bbase = Bx + (size_t)n0 * K;

    float acc[4][8][4];
    #pragma unroll
    for (int i = 0; i < 4; i++)
        #pragma unroll
        for (int j = 0; j < 8; j++) {
            acc[i][j][0] = 0.f; acc[i][j][1] = 0.f; acc[i][j][2] = 0.f; acc[i][j][3] = 0.f;
        }

    const int KT = K / BKT;
    // 2048 chunks of 16B per stage (A:1024, B:1024), 16 per thread
    #pragma unroll
    for (int p = 0; p < 2; p++) {
        uint32_t st = sbase + p * STAGE_B;
        #pragma unroll
        for (int i = 0; i < 16; i++) {
            int id = tid + (i << 7);
            if (id < 1024) {
                int row = id >> 3, c = id & 7;
                uint32_t soff = row * 128 + (((uint32_t)c ^ (row & 7)) << 4);
                cp16s(st + soff, Abase + (size_t)row * K + p * BKT + c * 8);
            } else {
                int idb = id - 1024;
                int row = idb >> 3, c = idb & 7;
                uint32_t soff = row * 128 + (((uint32_t)c ^ (row & 7)) << 4);
                cp16s(st + 16384 + soff, Bbase + (size_t)row * K + p * BKT + c * 8);
            }
        }
        CP_COMMIT();
    }

    int ldst = 2;   // stage index to load next
    for (int kt = 0; kt < KT; kt++) {
        if (kt + 2 < KT) {
            uint32_t st = sbase + ldst * STAGE_B;
            int koff = (kt + 2) * BKT;
            #pragma unroll
            for (int i = 0; i < 16; i++) {
                int id = tid + (i << 7);
                if (id < 1024) {
                    int row = id >> 3, c = id & 7;
                    uint32_t soff = row * 128 + (((uint32_t)c ^ (row & 7)) << 4);
                    cp16s(st + soff, Abase + (size_t)row * K + koff + c * 8);
                } else {
                    int idb = id - 1024;
                    int row = idb >> 3, c = idb & 7;
                    uint32_t soff = row * 128 + (((uint32_t)c ^ (row & 7)) << 4);
                    cp16s(st + 16384 + soff, Bbase + (size_t)row * K + koff + c * 8);
                }
            }
        }
        CP_COMMIT();
        asm volatile("cp.async.wait_group 2;");
        __syncthreads();

        int cur = ldst + 1; if (cur >= NSTAGE) cur -= NSTAGE;   // == kt % 3
        const uint32_t st = sbase + cur * STAGE_B;
        const uint32_t swz = lane & 7;
        #pragma unroll
        for (int ks = 0; ks < 4; ks++) {
            uint32_t a[4][4], b[8][2];
            #pragma unroll
            for (int mi = 0; mi < 4; mi++) {
                int row = wm + mi * 16 + (lane & 15);
                uint32_t ch = ((uint32_t)(2 * ks + (lane >> 4))) ^ swz;
                ldsm4(a[mi], st + row * 128 + (ch << 4));
            }
            #pragma unroll
            for (int ni = 0; ni < 8; ni += 2) {
                int row = wn + ni * 8 + ((lane >> 4) << 3) + (lane & 7);
                uint32_t ch = ((uint32_t)(2 * ks + ((lane >> 3) & 1))) ^ swz;
                uint32_t r4[4];
                ldsm4(r4, st + 16384 + row * 128 + (ch << 4));
                b[ni][0] = r4[0]; b[ni][1] = r4[1];
                b[ni+1][0] = r4[2]; b[ni+1][1] = r4[3];
            }
            #pragma unroll
            for (int mi = 0; mi < 4; mi++)
                #pragma unroll
                for (int ni = 0; ni < 8; ni++)
                    hmma(acc[mi][ni], a[mi], b[ni]);
        }
        __syncthreads();
        if (++ldst >= NSTAGE) ldst = 0;
    }

    // epilogue
    #pragma unroll
    for (int mi = 0; mi < 4; mi++) {
        #pragma unroll
        for (int ni = 0; ni < 8; ni++) {
            int r0 = m0 + wm + mi * 16 + (lane >> 2);
            int col = n0 + wn + ni * 8 + ((lane & 3) << 1);
            size_t i0 = (size_t)r0 * N + col;
            size_t i1 = i0 + (size_t)8 * N;
            float* cc = acc[mi][ni];
            if (mode == 1) {
                float2 r0v = *(const float2*)(R + i0);
                float2 r1v = *(const float2*)(R + i1);
                *(float2*)(C + i0) = make_float2(cc[0] + r0v.x, cc[1] + r0v.y);
                *(float2*)(C + i1) = make_float2(cc[2] + r1v.x, cc[3] + r1v.y);
            } else {
                *(__half2*)(OHx + i0) = __floats2half2_rn(cc[0], cc[1]);
                *(__half2*)(OHx + i1) = __floats2half2_rn(cc[2], cc[3]);
            }
        }
    }
}

// ---------------- fused gate+up GEMM with gelu-mul epilogue ----------------
// CTA tile 128(M) x 128(N), dual-B, 256 threads, 8 warps (64x32 each, 2x4),
// BK=64, 4-stage cp.async.
#define GU_STAGE ((128 + 128 + 128) * BKT * 2)   // 49152
#define GU_SMEM (4 * GU_STAGE)                   // 196608

__global__ __launch_bounds__(256, 1) void gemm_gateup(
    const __half* __restrict__ A, const __half* __restrict__ Bg,
    const __half* __restrict__ Bu, __half* __restrict__ OH, int K)
{
    extern __shared__ char smem[];
    const uint32_t sbase = (uint32_t)__cvta_generic_to_shared(smem);
    const int tid = threadIdx.x;
    const int lane = tid & 31, warp = tid >> 5;
    const int m0 = blockIdx.x * 128, n0 = blockIdx.y * 128;

    const int wm = (warp & 1) * 64;      // 0 or 64
    const int wn = (warp >> 1) * 32;     // 0,32,64,96

    const __half* Abase = A + (size_t)m0 * K;
    const __half* Gbase = Bg + (size_t)n0 * K;
    const __half* Ubase = Bu + (size_t)n0 * K;

    float accg[4][4][4], accu[4][4][4];
    #pragma unroll
    for (int i = 0; i < 4; i++)
        #pragma unroll
        for (int j = 0; j < 4; j++)
            #pragma unroll
            for (int c = 0; c < 4; c++) { accg[i][j][c] = 0.f; accu[i][j][c] = 0.f; }

    const int KT = K / BKT;
    // 3072 chunks/stage: A 0..1023, Bg 1024..2047, Bu 2048..3071; 12 per thread
    #pragma unroll
    for (int p = 0; p < 3; p++) {
        uint32_t st = sbase + p * GU_STAGE;
        #pragma unroll
        for (int i = 0; i < 12; i++) {
            int id = tid + (i << 8);
            int sel = id >> 10;           // 0=A,1=Bg,2=Bu
            int idl = id & 1023;
            int row = idl >> 3, c = idl & 7;
            uint32_t soff = (uint32_t)sel * 16384 + row * 128 + (((uint32_t)c ^ (row & 7)) << 4);
            const __half* gb = (sel == 0 ? Abase : (sel == 1 ? Gbase : Ubase));
            cp16s(st + soff, gb + (size_t)row * K + p * BKT + c * 8);
        }
        CP_COMMIT();
    }

    for (int kt = 0; kt < KT; kt++) {
        if (kt + 3 < KT) {
            uint32_t st = sbase + ((kt + 3) & 3) * GU_STAGE;
            int koff = (kt + 3) * BKT;
            #pragma unroll
            for (int i = 0; i < 12; i++) {
                int id = tid + (i << 8);
                int sel = id >> 10;
                int idl = id & 1023;
                int row = idl >> 3, c = idl & 7;
                uint32_t soff = (uint32_t)sel * 16384 + row * 128 + (((uint32_t)c ^ (row & 7)) << 4);
                const __half* gb = (sel == 0 ? Abase : (sel == 1 ? Gbase : Ubase));
                cp16s(st + soff, gb + (size_t)row * K + koff + c * 8);
            }
        }
        CP_COMMIT();
        asm volatile("cp.async.wait_group 3;");
        __syncthreads();

        const uint32_t st = sbase + (kt & 3) * GU_STAGE;
        const uint32_t swz = lane & 7;
        #pragma unroll
        for (int ks = 0; ks < 4; ks++) {
            uint32_t a[4][4], bg[4][2], bu[4][2];
            #pragma unroll
            for (int mi = 0; mi < 4; mi++) {
                int row = wm + mi * 16 + (lane & 15);
                uint32_t ch = ((uint32_t)(2 * ks + (lane >> 4))) ^ swz;
                ldsm4(a[mi], st + row * 128 + (ch << 4));
            }
            #pragma unroll
            for (int ni = 0; ni < 4; ni += 2) {
                int row = wn + ni * 8 + ((lane >> 4) << 3) + (lane & 7);
                uint32_t ch = ((uint32_t)(2 * ks + ((lane >> 3) & 1))) ^ swz;
                uint32_t r4[4];
                ldsm4(r4, st + 16384 + row * 128 + (ch << 4));
                bg[ni][0] = r4[0]; bg[ni][1] = r4[1];
                bg[ni+1][0] = r4[2]; bg[ni+1][1] = r4[3];
                ldsm4(r4, st + 32768 + row * 128 + (ch << 4));
                bu[ni][0] = r4[0]; bu[ni][1] = r4[1];
                bu[ni+1][0] = r4[2]; bu[ni+1][1] = r4[3];
            }
            #pragma unroll
            for (int mi = 0; mi < 4; mi++)
                #pragma unroll
                for (int ni = 0; ni < 4; ni++) {
                    hmma(accg[mi][ni], a[mi], bg[ni]);
                    hmma(accu[mi][ni], a[mi], bu[ni]);
                }
        }
        __syncthreads();
    }

    // epilogue: half(gelu(g) * u)
    #pragma unroll
    for (int mi = 0; mi < 4; mi++) {
        #pragma unroll
        for (int ni = 0; ni < 4; ni++) {
            int r0 = m0 + wm + mi * 16 + (lane >> 2);
            int col = n0 + wn + ni * 8 + ((lane & 3) << 1);
            size_t i0 = (size_t)r0 * INTER + col;
            size_t i1 = i0 + (size_t)8 * INTER;
            float* gg = accg[mi][ni];
            float* uu = accu[mi][ni];
            *(__half2*)(OH + i0) = __floats2half2_rn(gelu_tanh(gg[0]) * uu[0],
                                                     gelu_tanh(gg[1]) * uu[1]);
            *(__half2*)(OH + i1) = __floats2half2_rn(gelu_tanh(gg[2]) * uu[2],
                                                     gelu_tanh(gg[3]) * uu[3]);
        }
    }
}

// ---------------- attention: one block per (b,h), RoPE fused on load ----------------
#define ATTN_SMEM ((64*260 + 256*66 + 64*256 + 64*68) * 4)
__global__ __launch_bounds__(256) void attn_kernel(
    const __half* __restrict__ q, const __half* __restrict__ k, const __half* __restrict__ v,
    const float* __restrict__ mask, const int* __restrict__ pos_ids,
    const float* __restrict__ invf,
    float* __restrict__ attn_out, __half* __restrict__ ao)
{
    extern __shared__ float sm[];
    float* Qs = sm;                     // [64][260]
    float* Ks = Qs + 64 * 260;          // [256][66]
    float* Vs = Ks + 256 * 66;          // [64][256]
    float* AS = Vs + 64 * 256;          // [64][68]
    int h = blockIdx.x, b = blockIdx.y;
    int tid = threadIdx.x;
    const __half* qb = q + ((size_t)b * SDIM * HHE + h) * HD;
    const __half* kb = k + (size_t)b * SDIM * HD;
    const __half* vb = v + (size_t)b * SDIM * HD;
    for (int i = tid; i < 64 * 128; i += 256) {
        int r = i >> 7, d = i & 127;
        float p = (float)pos_ids[r * SDIM + b];
        float ang = p * invf[d];
        float c = cosf(ang), sn = sinf(ang);
        float q1 = __half2float(qb[(size_t)r * (HHE*HD) + d]);
        float q2 = __half2float(qb[(size_t)r * (HHE*HD) + d + 128]);
        Qs[r * 260 + d]       = q1 * c - q2 * sn;
        Qs[r * 260 + d + 128] = q2 * c + q1 * sn;
        float k1 = __half2float(kb[r * HD + d]);
        float k2 = __half2float(kb[r * HD + d + 128]);
        Ks[d * 66 + r]         = k1 * c - k2 * sn;
        Ks[(d + 128) * 66 + r] = k2 * c + k1 * sn;
    }
    for (int i = tid; i < 64 * 256; i += 256) Vs[i] = __half2float(vb[i]);
    __syncthreads();

    int qi = tid >> 2, part = tid & 3;
    float sc[16];
    #pragma unroll
    for (int j = 0; j < 16; j++) sc[j] = 0.f;
    const float* qrow = Qs + qi * 260;
    #pragma unroll 4
    for (int d = 0; d < 256; d++) {
        float qd = qrow[d];
        const float* kd = Ks + d * 66 + part;
        #pragma unroll
        for (int j = 0; j < 16; j++) sc[j] += qd * kd[4 * j];
    }
    const float* mrow = mask + ((size_t)b * 64 + qi) * 64;
    float sf[16];
    float mx = -INFINITY;
    #pragma unroll
    for (int j = 0; j < 16; j++) {
        int kj = part + 4 * j;
        float s = sc[j] * 0.0625f + mrow[kj];
        sf[j] = __half2float(__float2half(s));       // -1e9 -> -inf in f16
        mx = fmaxf(mx, sf[j]);
    }
    mx = fmaxf(mx, __shfl_xor_sync(0xffffffffu, mx, 1));
    mx = fmaxf(mx, __shfl_xor_sync(0xffffffffu, mx, 2));
    float sum = 0.f;
    #pragma unroll
    for (int j = 0; j < 16; j++) {
        float dd = __half2float(__float2half(sf[j] - mx));
        float e  = __half2float(__float2half(expf(dd)));
        sf[j] = e; sum += e;
    }
    sum += __shfl_xor_sync(0xffffffffu, sum, 1);
    sum += __shfl_xor_sync(0xffffffffu, sum, 2);
    float* asr = AS + qi * 68;
    float* aout = attn_out ? attn_out + (((size_t)b * HHE + h) * 64 + qi) * 64 : nullptr;
    #pragma unroll
    for (int j = 0; j < 16; j++) {
        int kj = part + 4 * j;
        float a = __half2float(__float2half(sf[j] / sum));
        asr[kj] = a;
        if (aout) aout[kj] = a;
    }
    __syncthreads();

    float acc[64];
    #pragma unroll
    for (int d2 = 0; d2 < 64; d2++) acc[d2] = 0.f;
    for (int kj = 0; kj < 64; kj++) {
        float av = asr[kj];
        const float* vr = Vs + kj * 256 + part;
        #pragma unroll
        for (int d2 = 0; d2 < 64; d2++) acc[d2] += av * vr[4 * d2];
    }
    __half* aorow = ao + (((size_t)b * 64 + qi) * HHE + h) * HD + part;
    #pragma unroll
    for (int d2 = 0; d2 < 64; d2++) aorow[4 * d2] = __float2half_rn(acc[d2]);
}

// ---------------- stream/event pool (lazy, created once; host code only runs
// during the correctness call and graph capture, never during replay) ----------
static cudaStream_t g_side = nullptr;
static cudaEvent_t g_ev_start, g_ev_qkv, g_ev_o, g_ev_gu, g_ev_d;
static bool g_stream_ok = false;

// ---------------- launch ----------------
extern "C" void kernel_launch(void* const* d_in, const int* in_sizes, int n_in,
                              void* d_out, int out_size) {
    const float* x      = (const float*)d_in[0];
    const float* mask   = (const float*)d_in[1];
    const int*   pos    = (const int*)  d_in[2];
    const float* invf   = (const float*)d_in[3];
    const float* wq     = (const float*)d_in[4];
    const float* wk     = (const float*)d_in[5];
    const float* wv     = (const float*)d_in[6];
    const float* wo     = (const float*)d_in[7];
    const float* wgate  = (const float*)d_in[8];
    const float* wup    = (const float*)d_in[9];
    const float* wdown  = (const float*)d_in[10];
    const float* ln1    = (const float*)d_in[11];
    const float* ln2    = (const float*)d_in[12];

    float* out = (float*)d_out;
    float* out_h = out;
    const int HID_N = ROWS * DDIM;
    const int ATT_N = BDIM * HHE * SDIM * SDIM;
    float* out_attn = (out_size >= HID_N + ATT_N) ? out + HID_N : nullptr;

    __half *h1h, *qh, *kh, *vh, *aoh, *mlph, *wqh, *wkh, *wvh, *woh, *wgh, *wuh, *wdh;
    cudaGetSymbolAddress((void**)&h1h,  g_h1h);
    cudaGetSymbolAddress((void**)&qh,   g_qh);
    cudaGetSymbolAddress((void**)&kh,   g_kh);
    cudaGetSymbolAddress((void**)&vh,   g_vh);
    cudaGetSymbolAddress((void**)&aoh,  g_aoh);
    cudaGetSymbolAddress((void**)&mlph, g_mlph);
    cudaGetSymbolAddress((void**)&wqh,  g_wqh);
    cudaGetSymbolAddress((void**)&wkh,  g_wkh);
    cudaGetSymbolAddress((void**)&wvh,  g_wvh);
    cudaGetSymbolAddress((void**)&woh,  g_woh);
    cudaGetSymbolAddress((void**)&wgh,  g_wgh);
    cudaGetSymbolAddress((void**)&wuh,  g_wuh);
    cudaGetSymbolAddress((void**)&wdh,  g_wdh);

    cudaFuncSetAttribute(attn_kernel, cudaFuncAttributeMaxDynamicSharedMemorySize, ATTN_SMEM);
    cudaFuncSetAttribute(gemm_h, cudaFuncAttributeMaxDynamicSharedMemorySize, GEMM_SMEM);
    cudaFuncSetAttribute(gemm_gateup, cudaFuncAttributeMaxDynamicSharedMemorySize, GU_SMEM);

    // lazy stream/event setup (no device memory involved)
    if (!g_side && !g_stream_ok) {
        bool ok = true;
        ok &= (cudaStreamCreateWithFlags(&g_side, cudaStreamNonBlocking) == cudaSuccess);
        ok &= (cudaEventCreateWithFlags(&g_ev_start, cudaEventDisableTiming) == cudaSuccess);
        ok &= (cudaEventCreateWithFlags(&g_ev_qkv,   cudaEventDisableTiming) == cudaSuccess);
        ok &= (cudaEventCreateWithFlags(&g_ev_o,     cudaEventDisableTiming) == cudaSuccess);
        ok &= (cudaEventCreateWithFlags(&g_ev_gu,    cudaEventDisableTiming) == cudaSuccess);
        ok &= (cudaEventCreateWithFlags(&g_ev_d,     cudaEventDisableTiming) == cudaSuccess);
        g_stream_ok = ok;
        if (!ok) g_side = nullptr;
    }
    const bool fork = (g_side != nullptr);

    auto cv = [&](const float* src, __half* dst, size_t n, cudaStream_t s) {
        int n8 = (int)(n / 8);
        cvt_h_kernel<<<(n8 + 255) / 256, 256, 0, s>>>((const float4*)src, (half2x4*)dst, n8);
    };

    if (fork) {
        // fork side stream into the capture
        cudaEventRecord(g_ev_start, 0);
        cudaStreamWaitEvent(g_side, g_ev_start, 0);
        // side stream: all weight converts, events at dependency boundaries
        cv(wq, wqh, (size_t)DDIM*DDIM, g_side);
        cv(wk, wkh, (size_t)HD*DDIM,   g_side);
        cv(wv, wvh, (size_t)HD*DDIM,   g_side);
        cudaEventRecord(g_ev_qkv, g_side);
        cv(wo, woh, (size_t)DDIM*DDIM, g_side);
        cudaEventRecord(g_ev_o, g_side);
        cv(wgate, wgh, (size_t)INTER*DDIM, g_side);
        cv(wup,   wuh, (size_t)INTER*DDIM, g_side);
        cudaEventRecord(g_ev_gu, g_side);
        cv(wdown, wdh, (size_t)DDIM*INTER, g_side);
        cudaEventRecord(g_ev_d, g_side);
    } else {
        cv(wq, wqh, (size_t)DDIM*DDIM, 0);
        cv(wk, wkh, (size_t)HD*DDIM,   0);
        cv(wv, wvh, (size_t)HD*DDIM,   0);
        cv(wo, woh, (size_t)DDIM*DDIM, 0);
        cv(wgate, wgh, (size_t)INTER*DDIM, 0);
        cv(wup,   wuh, (size_t)INTER*DDIM, 0);
        cv(wdown, wdh, (size_t)DDIM*INTER, 0);
    }

    // main stream: compute chain
    rmsnorm_kernel<<<ROWS, 256>>>(x, ln1, (__half2*)h1h);
    if (fork) cudaStreamWaitEvent(0, g_ev_qkv, 0);
    gemm_h<<<dim3(ROWS/128, DDIM/128), 128, GEMM_SMEM>>>(h1h, wqh, nullptr, nullptr,
                                                         nullptr, qh, nullptr, DDIM, DDIM, 3);
    gemm_h<<<dim3(ROWS/128, HD/128, 2), 128, GEMM_SMEM>>>(h1h, wkh, wvh, nullptr,
                                                          nullptr, kh, vh, HD, DDIM, 3);
    attn_kernel<<<dim3(HHE, BDIM), 256, ATTN_SMEM>>>(qh, kh, vh, mask, pos, invf, out_attn, aoh);
    if (fork) cudaStreamWaitEvent(0, g_ev_o, 0);
    gemm_h<<<dim3(ROWS/128, DDIM/128), 128, GEMM_SMEM>>>(aoh, woh, nullptr, out_h,
                                                         x, nullptr, nullptr, DDIM, DDIM, 1);
    rmsnorm_kernel<<<ROWS, 256>>>(out_h, ln2, (__half2*)h1h);
    if (fork) cudaStreamWaitEvent(0, g_ev_gu, 0);
    gemm_gateup<<<dim3(ROWS/128, INTER/128), 256, GU_SMEM>>>(h1h, wgh, wuh, mlph, DDIM);
    if (fork) cudaStreamWaitEvent(0, g_ev_d, 0);
    gemm_h<<<dim3(ROWS/128, DDIM/128), 128, GEMM_SMEM>>>(mlph, wdh, nullptr, out_h,
                                                         out_h, nullptr, nullptr, DDIM, INTER, 1);
}